// round 8
// baseline (speedup 1.0000x reference)
#include <cuda_runtime.h>
#include <cstdint>

#define NQ     4096
#define NDB    65536
#define DIM    32
#define DAUX   32
#define KNN    5
#define QPB    32            // queries per block
#define PBLK   512           // db points per p-block
#define NBLK   (NDB / PBLK)  // 128
#define THREADS 1024
#define BIGF   3.0e38f

// dynamic smem layout (byte offsets)
#define SM_TI     0                        // 4q * 5k * 1024 thr * 4B = 81920
#define SM_QT     81920                    // 32 d * 32 q * 4B = 4096
#define SM_CS     86016                    // 32 q * 20 cand * 4B = 2560
#define SM_CI     88576                    // 2560
#define SM_TOTAL  91136

// Scratch: db transposed [dim][point]; row 32 holds 0.5*||db||^2.
__device__ float g_dbT[33 * NDB];

// ---------------------------------------------------------------------------
// Prep: tiled transpose of db [65536][32] -> g_dbT [33][65536] (+ half-sq row)
// ---------------------------------------------------------------------------
__global__ void prep_kernel(const float* __restrict__ db) {
    __shared__ float t[32][33];
    const int p0 = blockIdx.x * 32;
    const int tx = threadIdx.x & 31;
    const int ty = threadIdx.x >> 5;     // 0..7

#pragma unroll
    for (int r = 0; r < 4; ++r) {
        int row = ty + r * 8;
        t[tx][row] = db[(p0 + row) * DIM + tx];
    }
    __syncthreads();
#pragma unroll
    for (int r = 0; r < 4; ++r) {
        int d = ty + r * 8;
        g_dbT[d * NDB + p0 + tx] = t[d][tx];
    }
    if (ty == 0) {
        float s = 0.f;
#pragma unroll
        for (int d = 0; d < 32; ++d) { float v = t[d][tx]; s += v * v; }
        g_dbT[32 * NDB + p0 + tx] = 0.5f * s;
    }
}

// ---------------------------------------------------------------------------
// helpers
// ---------------------------------------------------------------------------
__device__ __forceinline__ unsigned long long dup2(float x) {
    unsigned int u = __float_as_uint(x);
    unsigned long long r;
    asm("mov.b64 %0, {%1, %1};" : "=l"(r) : "r"(u));
    return r;
}
__device__ __forceinline__ void fma2(unsigned long long& a,
                                     unsigned long long x, unsigned long long y) {
    asm("fma.rn.f32x2 %0, %1, %2, %0;" : "+l"(a) : "l"(x), "l"(y));
}
__device__ __forceinline__ void unpack2(unsigned long long v, float& lo, float& hi) {
    unsigned int a, b;
    asm("mov.b64 {%0, %1}, %2;" : "=r"(a), "=r"(b) : "l"(v));
    lo = __uint_as_float(a);
    hi = __uint_as_float(b);
}

// top-5 insert: scores sorted-ascending in registers, indexes in smem
// ([slot][tid] layout -> conflict-free). Hot path: 1 compare, untaken branch.
#define TIX(A, K) ti_sm[((A) * 5 + (K)) * THREADS + tid]
#define TOPK_INS(A, SC, PI) do {                                                \
    if ((SC) < ts[A][4]) {                                                      \
        float s_ = (SC); int pi_ = (PI);                                        \
        if (s_ < ts[A][3]) {                                                    \
            ts[A][4] = ts[A][3]; TIX(A,4) = TIX(A,3);                           \
            if (s_ < ts[A][2]) {                                                \
                ts[A][3] = ts[A][2]; TIX(A,3) = TIX(A,2);                       \
                if (s_ < ts[A][1]) {                                            \
                    ts[A][2] = ts[A][1]; TIX(A,2) = TIX(A,1);                   \
                    if (s_ < ts[A][0]) {                                        \
                        ts[A][1] = ts[A][0]; TIX(A,1) = TIX(A,0);               \
                        ts[A][0] = s_; TIX(A,0) = pi_;                          \
                    } else { ts[A][1] = s_; TIX(A,1) = pi_; }                   \
                } else { ts[A][2] = s_; TIX(A,2) = pi_; }                       \
            } else { ts[A][3] = s_; TIX(A,3) = pi_; }                           \
        } else { ts[A][4] = s_; TIX(A,4) = pi_; }                               \
    } } while (0)

// ---------------------------------------------------------------------------
// Main: 1024 threads (32 warps, occ 50%), 32 queries/block, db streamed
// directly from global (L1/L2-resident), per-thread 4q x 4p f32x2 micro-tile.
// ---------------------------------------------------------------------------
__global__ void __launch_bounds__(THREADS, 1)
knn_kernel(const float* __restrict__ q,
           const float* __restrict__ aux,
           float* __restrict__ out) {
    extern __shared__ char smem[];
    int*   ti_sm = (int*)  (smem + SM_TI);    // [4][5][1024]
    float* q_t   = (float*)(smem + SM_QT);    // [32 d][32 q]
    float* cs    = (float*)(smem + SM_CS);    // [32 q][20]
    int*   ci    = (int*)  (smem + SM_CI);    // [32 q][20]

    const int tid  = threadIdx.x;
    const int lane = tid & 31;
    const int pg   = tid & 127;            // point group: pg*4 .. +3 within p-block
    const int qg   = tid >> 7;             // query group 0..7: queries qg*4 .. +3
    const int q0   = blockIdx.x * QPB;

    // q tile transposed into smem [d][q]
    {
        int row = tid >> 5;                // query
        int col = tid & 31;                // dim
        q_t[col * 32 + row] = q[(q0 + row) * DIM + col];
    }
    // init smem idx lists
#pragma unroll
    for (int k = 0; k < 20; ++k) ti_sm[k * THREADS + tid] = 0;
    __syncthreads();

    float ts[4][5];
#pragma unroll
    for (int a = 0; a < 4; ++a)
#pragma unroll
        for (int b = 0; b < 5; ++b) ts[a][b] = BIGF;

    for (int b = 0; b < NBLK; ++b) {
        if ((b & 1) == 0) __syncthreads();          // drift control (L1 reuse window)

        const float* pbp = g_dbT + b * PBLK + pg * 4;

        unsigned long long acc[4][2];
#pragma unroll
        for (int a = 0; a < 4; ++a) { acc[a][0] = 0ull; acc[a][1] = 0ull; }

#pragma unroll
        for (int d = 0; d < 32; ++d) {
            float4 qv = *(const float4*)(q_t + d * 32 + qg * 4);   // LDS broadcast
            unsigned long long qa = dup2(qv.x);
            unsigned long long qb = dup2(qv.y);
            unsigned long long qc = dup2(qv.z);
            unsigned long long qd = dup2(qv.w);
            ulonglong2 dv = *(const ulonglong2*)(pbp + d * NDB);   // LDG.128 (L1/L2 hit)
            fma2(acc[0][0], qa, dv.x); fma2(acc[0][1], qa, dv.y);
            fma2(acc[1][0], qb, dv.x); fma2(acc[1][1], qb, dv.y);
            fma2(acc[2][0], qc, dv.x); fma2(acc[2][1], qc, dv.y);
            fma2(acc[3][0], qd, dv.x); fma2(acc[3][1], qd, dv.y);
        }

        // score = 0.5||db||^2 - q.db (monotone in distance per query)
        float4 hs = *(const float4*)(g_dbT + 32 * NDB + b * PBLK + pg * 4);
        const int pb = b * PBLK + pg * 4;
#pragma unroll
        for (int a = 0; a < 4; ++a) {
            float v0, v1, v2, v3;
            unpack2(acc[a][0], v0, v1);
            unpack2(acc[a][1], v2, v3);
            float s0 = hs.x - v0, s1 = hs.y - v1, s2 = hs.z - v2, s3 = hs.w - v3;
            TOPK_INS(a, s0, pb + 0);
            TOPK_INS(a, s1, pb + 1);
            TOPK_INS(a, s2, pb + 2);
            TOPK_INS(a, s3, pb + 3);
        }
    }
    __syncthreads();

    // ---- stage 1: per-warp merge of top-5 lists; 4 warps per query-group ----
    const unsigned FULL = 0xffffffffu;
    const int wp = (tid >> 5) & 3;         // warp within the q-group (0..3)
#pragma unroll
    for (int a = 0; a < 4; ++a) {
        const int ql = qg * 4 + a;         // query within block

        float c0 = ts[a][0], c1 = ts[a][1], c2 = ts[a][2], c3 = ts[a][3], c4 = ts[a][4];
        int   j0 = TIX(a, 0), j1 = TIX(a, 1), j2 = TIX(a, 2), j3 = TIX(a, 3), j4 = TIX(a, 4);

#pragma unroll
        for (int k = 0; k < KNN; ++k) {
            float m  = c0;
            int   ml = lane;
#pragma unroll
            for (int off = 16; off; off >>= 1) {
                float om = __shfl_xor_sync(FULL, m, off);
                int   ol = __shfl_xor_sync(FULL, ml, off);
                if (om < m || (om == m && ol < ml)) { m = om; ml = ol; }
            }
            int wi = __shfl_sync(FULL, j0, ml);
            if (lane == k) { cs[ql * 20 + wp * 5 + k] = m; ci[ql * 20 + wp * 5 + k] = wi; }
            if (lane == ml) {
                c0 = c1; c1 = c2; c2 = c3; c3 = c4; c4 = BIGF;
                j0 = j1; j1 = j2; j2 = j3; j3 = j4;
            }
        }
    }
    __syncthreads();

    // ---- stage 2: one warp per query merges 20 candidates, gathers aux ----
    {
        const int w    = tid >> 5;         // 0..31 == query within block
        const int qidx = q0 + w;

        float sc = (lane < 20) ? cs[w * 20 + lane] : BIGF;
        int   id = (lane < 20) ? ci[w * 20 + lane] : 0;

        // ||q||^2 via warp reduction (lane = dim)
        float qv  = q[qidx * DIM + lane];
        float qsq = qv * qv;
#pragma unroll
        for (int off = 16; off; off >>= 1)
            qsq += __shfl_xor_sync(FULL, qsq, off);

        float wk[KNN]; int bk[KNN];
        float wsum = 0.f;
#pragma unroll
        for (int k = 0; k < KNN; ++k) {
            float m  = sc;
            int   ml = lane;
#pragma unroll
            for (int off = 16; off; off >>= 1) {
                float om = __shfl_xor_sync(FULL, m, off);
                int   ol = __shfl_xor_sync(FULL, ml, off);
                if (om < m || (om == m && ol < ml)) { m = om; ml = ol; }
            }
            int wi = __shfl_sync(FULL, id, ml);
            float dist = sqrtf(fmaxf(qsq + 2.0f * m, 0.0f));
            float wgt  = 1.0f / (dist + 1e-6f);
            wk[k] = wgt; bk[k] = wi; wsum += wgt;
            if (lane == ml) sc = BIGF;     // pop winner
        }

        float acc_o = 0.f;
#pragma unroll
        for (int k = 0; k < KNN; ++k)
            acc_o += wk[k] * aux[bk[k] * DAUX + lane];
        out[qidx * DAUX + lane] = acc_o / wsum;
    }
}

// ---------------------------------------------------------------------------
extern "C" void kernel_launch(void* const* d_in, const int* in_sizes, int n_in,
                              void* d_out, int out_size) {
    const float* q   = (const float*)d_in[0];   // embedding_features [4096,32]
    const float* db  = (const float*)d_in[1];   // db_embedding      [65536,32]
    const float* aux = (const float*)d_in[2];   // auxiliary_features[65536,32]
    float* out = (float*)d_out;                 // [4096,32]

    cudaFuncSetAttribute(knn_kernel, cudaFuncAttributeMaxDynamicSharedMemorySize,
                         SM_TOTAL);

    prep_kernel<<<NDB / 32, 256>>>(db);
    knn_kernel<<<NQ / QPB, THREADS, SM_TOTAL>>>(q, aux, out);
}